// round 7
// baseline (speedup 1.0000x reference)
#include <cuda_runtime.h>
#include <cuda_bf16.h>

// Problem dims
#define Bn   8
#define Nn   6
#define Dn   41
#define FHn  8
#define FWn  22
#define Cn   64
#define NX0  200
#define NX1  200

constexpr int NPRIME      = Bn * Nn * Dn * FHn * FWn;     // 346368 (=1353*256)
constexpr int PTS_PER_B   = Nn * Dn * FHn * FWn;          // 43296
constexpr int PTS_PER_N   = Dn * FHn * FWn;               // 7216
constexpr int PTS_PER_D   = FHn * FWn;                    // 176
constexpr int VOX_PER_B   = NX0 * NX1;                    // 40000
constexpr int TILES_PER_B = VOX_PER_B / 64;               // 625
constexpr int NTILES      = Bn * TILES_PER_B;             // 5000
constexpr int CAP         = 4096;                          // max pts per tile

// All state re-initialized at the START of each call (self-contained).
__device__ int g_tcount[NTILES];
__device__ int g_idx[(size_t)NTILES * CAP];   // packed (p<<6 | localvox)
__device__ float g_mats[48 * 24];             // M1[9], t1[3], M2[9], trans[3]

// ---------------------------------------------------------------------------
__device__ __forceinline__ void inv3(const float* m, float* o) {
    float a = m[0], b = m[1], c = m[2];
    float d = m[3], e = m[4], f = m[5];
    float g = m[6], h = m[7], i = m[8];
    float A  = e * i - f * h;
    float Bc = -(d * i - f * g);
    float Cc = d * h - e * g;
    float det = a * A + b * Bc + c * Cc;
    float inv = 1.0f / det;
    o[0] = A * inv;            o[1] = (c * h - b * i) * inv; o[2] = (b * f - c * e) * inv;
    o[3] = Bc * inv;           o[4] = (a * i - c * g) * inv; o[5] = (c * d - a * f) * inv;
    o[6] = Cc * inv;           o[7] = (b * g - a * h) * inv; o[8] = (a * e - b * d) * inv;
}

// K0: clear tile counts; block 0 computes camera matrices.
__global__ void init_kernel(const float* __restrict__ rots,
                            const float* __restrict__ trans,
                            const float* __restrict__ intrins,
                            const float* __restrict__ post_rots,
                            const float* __restrict__ post_trans) {
    int i = blockIdx.x * blockDim.x + threadIdx.x;
    if (i < NTILES) g_tcount[i] = 0;

    if (blockIdx.x == 0 && threadIdx.x < Bn * Nn) {
        int cam = threadIdx.x;
        float M1[9], Ki[9], M2[9];
        inv3(post_rots + cam * 9, M1);
        inv3(intrins + cam * 9, Ki);
        const float* R = rots + cam * 9;
        #pragma unroll
        for (int r = 0; r < 3; r++)
            #pragma unroll
            for (int c = 0; c < 3; c++)
                M2[r * 3 + c] = R[r * 3 + 0] * Ki[0 + c] + R[r * 3 + 1] * Ki[3 + c] + R[r * 3 + 2] * Ki[6 + c];
        const float* pt = post_trans + cam * 3;
        float t1[3];
        #pragma unroll
        for (int r = 0; r < 3; r++)
            t1[r] = M1[r * 3 + 0] * pt[0] + M1[r * 3 + 1] * pt[1] + M1[r * 3 + 2] * pt[2];

        float* o = g_mats + cam * 24;
        #pragma unroll
        for (int k = 0; k < 9; k++) o[k] = M1[k];
        #pragma unroll
        for (int k = 0; k < 3; k++) o[9 + k] = t1[k];
        #pragma unroll
        for (int k = 0; k < 9; k++) o[12 + k] = M2[k];
        const float* tr = trans + cam * 3;
        #pragma unroll
        for (int k = 0; k < 3; k++) o[21 + k] = tr[k];
    }
}

// ---------------------------------------------------------------------------
// K1: geometry once per point; kept -> per-tile list via warp-aggregated
// atomics (__match_any_sync on tile id kills hot-tile contention).
__global__ void geom_bin_kernel() {
    int p = blockIdx.x * blockDim.x + threadIdx.x;   // NPRIME is 256-divisible
    int lane = threadIdx.x & 31;

    int b  = p / PTS_PER_B;
    int r  = p - b * PTS_PER_B;
    int n  = r / PTS_PER_N;
    int r2 = r - n * PTS_PER_N;
    int d  = r2 / PTS_PER_D;
    int r3 = r2 - d * PTS_PER_D;
    int h  = r3 / FWn;
    int w  = r3 - h * FWn;

    const float* M = g_mats + (b * Nn + n) * 24;

    float fx = (float)w * (351.0f / 21.0f);
    float fy = (float)h * (127.0f / 7.0f);
    float fd = 4.0f + (float)d;

    // pt = inv(post_rots) @ (f - post_trans)  ==  M1 @ f - t1
    float px = M[0] * fx + M[1] * fy + M[2] * fd - M[9];
    float py = M[3] * fx + M[4] * fy + M[5] * fd - M[10];
    float pz = M[6] * fx + M[7] * fy + M[8] * fd - M[11];

    // unproject + rotate to ego frame
    float x2 = px * pz;
    float y2 = py * pz;
    float z2 = pz;
    float gxw = M[12] * x2 + M[13] * y2 + M[14] * z2 + M[21];
    float gyw = M[15] * x2 + M[16] * y2 + M[17] * z2 + M[22];
    float gzw = M[18] * x2 + M[19] * y2 + M[20] * z2 + M[23];

    // voxelize (truncate toward zero matches astype(int32))
    int gx = (int)((gxw + 50.0f) / 0.5f);
    int gy = (int)((gyw + 50.0f) / 0.5f);
    int gz = (int)((gzw + 10.0f) / 20.0f);

    bool kept = (gx >= 0) && (gx < NX0) && (gy >= 0) && (gy < NX1) && (gz == 0);

    unsigned kmask = __ballot_sync(0xffffffffu, kept);
    if (!kept) return;

    int voxInB = gx * NX1 + gy;
    int tileId = b * TILES_PER_B + (voxInB >> 6);
    int pos    = voxInB & 63;

    unsigned peers = __match_any_sync(kmask, tileId);
    int leaderLane = __ffs(peers) - 1;
    int rank = __popc(peers & ((1u << lane) - 1u));
    int base = 0;
    if (lane == leaderLane)
        base = atomicAdd(&g_tcount[tileId], __popc(peers));
    base = __shfl_sync(peers, base, leaderLane);

    int slot = base + rank;
    if (slot < CAP)
        g_idx[(size_t)tileId * CAP + slot] = (p << 6) | pos;
}

// ---------------------------------------------------------------------------
// K2: gather. One block per 64-voxel tile; 16 lane-groups stride the tile's
// point list jointly, accumulate via smem float atomics, transposed write.
__global__ void gather_kernel(const float4* __restrict__ feats,
                              float* __restrict__ out) {
    __shared__ float tile[64][65];
    int blk  = blockIdx.x;                 // NTILES
    int b    = blk / TILES_PER_B;
    int tIdx = blk - b * TILES_PER_B;
    int pos0 = tIdx * 64;
    int t    = threadIdx.x;                // 256
    int g    = t >> 4;                     // group 0..15
    int q    = t & 15;                     // channel-quad 0..15

    float* dst = out + (size_t)b * Cn * VOX_PER_B + pos0;

    int n = g_tcount[blk];
    if (n > CAP) n = CAP;

    if (n == 0) {                          // empty tile: zeros straight out
        float4 z = make_float4(0.f, 0.f, 0.f, 0.f);
        #pragma unroll
        for (int k = 0; k < 4; k++) {
            int i = t + 256 * k;
            int c = i >> 4;
            int p = (i & 15) * 4;
            __stcs(reinterpret_cast<float4*>(dst + (size_t)c * VOX_PER_B + p), z);
        }
        return;
    }

    // zero the smem tile
    #pragma unroll
    for (int k = 0; k < 17; k++) {
        int i = t + 256 * k;               // 64*65 = 4160
        if (i < 64 * 65) (&tile[0][0])[i] = 0.0f;
    }
    __syncthreads();

    const int* lst = g_idx + (size_t)blk * CAP;
    for (int j = g; j < n; j += 16) {
        int e   = lst[j];                  // broadcast within group
        int p   = e >> 6;
        int pos = e & 63;
        float4 v = __ldcs(&feats[p * 16 + q]);
        atomicAdd(&tile[pos][q * 4 + 0], v.x);
        atomicAdd(&tile[pos][q * 4 + 1], v.y);
        atomicAdd(&tile[pos][q * 4 + 2], v.z);
        atomicAdd(&tile[pos][q * 4 + 3], v.w);
    }
    __syncthreads();

    #pragma unroll
    for (int k = 0; k < 4; k++) {
        int i = t + 256 * k;               // 0..1023 float4 slots
        int c = i >> 4;
        int p = (i & 15) * 4;
        float4 v = make_float4(tile[p + 0][c], tile[p + 1][c],
                               tile[p + 2][c], tile[p + 3][c]);
        __stcs(reinterpret_cast<float4*>(dst + (size_t)c * VOX_PER_B + p), v);
    }
}

// ---------------------------------------------------------------------------
extern "C" void kernel_launch(void* const* d_in, const int* in_sizes, int n_in,
                              void* d_out, int out_size) {
    const float* x_feats    = (const float*)d_in[0];
    const float* rots       = (const float*)d_in[1];
    const float* trans      = (const float*)d_in[2];
    const float* intrins    = (const float*)d_in[3];
    const float* post_rots  = (const float*)d_in[4];
    const float* post_trans = (const float*)d_in[5];
    float* out = (float*)d_out;

    init_kernel<<<(NTILES + 255) / 256, 256>>>(rots, trans, intrins,
                                               post_rots, post_trans);
    geom_bin_kernel<<<NPRIME / 256, 256>>>();
    gather_kernel<<<NTILES, 256>>>(reinterpret_cast<const float4*>(x_feats), out);
}

// round 8
// speedup vs baseline: 1.6169x; 1.6169x over previous
#include <cuda_runtime.h>
#include <cuda_bf16.h>

// Problem dims
#define Bn   8
#define Nn   6
#define Dn   41
#define FHn  8
#define FWn  22
#define Cn   64
#define NX0  200
#define NX1  200

constexpr int NPRIME      = Bn * Nn * Dn * FHn * FWn;     // 346368 (=1353*256)
constexpr int PTS_PER_B   = Nn * Dn * FHn * FWn;          // 43296
constexpr int PTS_PER_N   = Dn * FHn * FWn;               // 7216
constexpr int PTS_PER_D   = FHn * FWn;                    // 176
constexpr int VOX_PER_B   = NX0 * NX1;                    // 40000
constexpr int GRID_FLOATS = Bn * VOX_PER_B * Cn;          // 20,480,000
constexpr int TILES_PER_B = VOX_PER_B / 64;               // 625
constexpr int NTILES      = Bn * TILES_PER_B;             // 5000
constexpr int SCAT_BLOCKS = 3520;                          // ~1 unit per thread

// All state re-initialized at the START of each call (self-contained).
__device__ __align__(16) float g_scratch[GRID_FLOATS];
__device__ unsigned int g_touched[NTILES];
__device__ int g_nkept;
__device__ int2 g_list[NPRIME];       // (point, global voxel)

// ---------------------------------------------------------------------------
__device__ __forceinline__ void inv3(const float* m, float* o) {
    float a = m[0], b = m[1], c = m[2];
    float d = m[3], e = m[4], f = m[5];
    float g = m[6], h = m[7], i = m[8];
    float A  = e * i - f * h;
    float Bc = -(d * i - f * g);
    float Cc = d * h - e * g;
    float det = a * A + b * Bc + c * Cc;
    float inv = 1.0f / det;
    o[0] = A * inv;            o[1] = (c * h - b * i) * inv; o[2] = (b * f - c * e) * inv;
    o[3] = Bc * inv;           o[4] = (a * i - c * g) * inv; o[5] = (c * d - a * f) * inv;
    o[6] = Cc * inv;           o[7] = (b * g - a * h) * inv; o[8] = (a * e - b * d) * inv;
}

// K0: pure clear (no serial matrix tail).
__global__ void init_kernel() {
    int i = blockIdx.x * blockDim.x + threadIdx.x;
    if (i < NTILES) g_touched[i] = 0;
    if (i == 0) g_nkept = 0;
}

// ---------------------------------------------------------------------------
// K1: per-block camera matrices in smem (latency overlapped across 1353
// blocks), geometry once per point, kept -> compact list + touched flag.
__global__ void geom_kernel(const float* __restrict__ rots,
                            const float* __restrict__ trans,
                            const float* __restrict__ intrins,
                            const float* __restrict__ post_rots,
                            const float* __restrict__ post_trans) {
    __shared__ float sM[48 * 24];
    int t = threadIdx.x;

    if (t < Bn * Nn) {
        int cam = t;
        float M1[9], Ki[9], M2[9];
        inv3(post_rots + cam * 9, M1);
        inv3(intrins + cam * 9, Ki);
        const float* R = rots + cam * 9;
        #pragma unroll
        for (int r = 0; r < 3; r++)
            #pragma unroll
            for (int c = 0; c < 3; c++)
                M2[r * 3 + c] = R[r * 3 + 0] * Ki[0 + c] + R[r * 3 + 1] * Ki[3 + c] + R[r * 3 + 2] * Ki[6 + c];
        const float* pt = post_trans + cam * 3;
        float t1[3];
        #pragma unroll
        for (int r = 0; r < 3; r++)
            t1[r] = M1[r * 3 + 0] * pt[0] + M1[r * 3 + 1] * pt[1] + M1[r * 3 + 2] * pt[2];

        float* o = sM + cam * 24;
        #pragma unroll
        for (int k = 0; k < 9; k++) o[k] = M1[k];
        #pragma unroll
        for (int k = 0; k < 3; k++) o[9 + k] = t1[k];
        #pragma unroll
        for (int k = 0; k < 9; k++) o[12 + k] = M2[k];
        const float* tr = trans + cam * 3;
        #pragma unroll
        for (int k = 0; k < 3; k++) o[21 + k] = tr[k];
    }
    __syncthreads();

    int p = blockIdx.x * blockDim.x + t;   // NPRIME is 256-divisible

    int b  = p / PTS_PER_B;
    int r  = p - b * PTS_PER_B;
    int n  = r / PTS_PER_N;
    int r2 = r - n * PTS_PER_N;
    int d  = r2 / PTS_PER_D;
    int r3 = r2 - d * PTS_PER_D;
    int h  = r3 / FWn;
    int w  = r3 - h * FWn;

    const float* M = sM + (b * Nn + n) * 24;

    float fx = (float)w * (351.0f / 21.0f);
    float fy = (float)h * (127.0f / 7.0f);
    float fd = 4.0f + (float)d;

    // pt = inv(post_rots) @ (f - post_trans)  ==  M1 @ f - t1
    float px = M[0] * fx + M[1] * fy + M[2] * fd - M[9];
    float py = M[3] * fx + M[4] * fy + M[5] * fd - M[10];
    float pz = M[6] * fx + M[7] * fy + M[8] * fd - M[11];

    // unproject + rotate to ego frame
    float x2 = px * pz;
    float y2 = py * pz;
    float z2 = pz;
    float gxw = M[12] * x2 + M[13] * y2 + M[14] * z2 + M[21];
    float gyw = M[15] * x2 + M[16] * y2 + M[17] * z2 + M[22];
    float gzw = M[18] * x2 + M[19] * y2 + M[20] * z2 + M[23];

    // voxelize (truncate toward zero matches astype(int32))
    int gx = (int)((gxw + 50.0f) / 0.5f);
    int gy = (int)((gyw + 50.0f) / 0.5f);
    int gz = (int)((gzw + 10.0f) / 20.0f);

    if (gx < 0 || gx >= NX0 || gy < 0 || gy >= NX1 || gz != 0) return;

    int voxInB = gx * NX1 + gy;
    int vox    = b * VOX_PER_B + voxInB;
    g_touched[vox >> 6] = 1;               // idempotent

    int slot = atomicAdd(&g_nkept, 1);     // ptxas warp-aggregates
    g_list[slot] = make_int2(p, vox);
}

// ---------------------------------------------------------------------------
// K2: zero scratch ONLY for touched tiles (16 KB per tile).
__global__ void zero_touched_kernel() {
    int blk = blockIdx.x;                  // NTILES
    if (g_touched[blk] == 0) return;
    float4* dst = reinterpret_cast<float4*>(g_scratch) + (size_t)blk * 1024;
    int t = threadIdx.x;                   // 256
    float4 z = make_float4(0.f, 0.f, 0.f, 0.f);
    #pragma unroll
    for (int k = 0; k < 4; k++) dst[t + 256 * k] = z;
}

// ---------------------------------------------------------------------------
// K3: scatter kept points, 16 lanes per point, ~1 unit per thread.
__global__ void scatter_kernel(const float4* __restrict__ feats) {
    int total  = g_nkept * 16;
    int stride = gridDim.x * blockDim.x;
    for (int i = blockIdx.x * blockDim.x + threadIdx.x; i < total; i += stride) {
        int s = i >> 4;
        int q = i & 15;
        int2 e = g_list[s];                // one 8B load, broadcast in group
        float4 v = __ldcs(&feats[e.x * 16 + q]);
        atomicAdd(reinterpret_cast<float4*>(g_scratch) + (size_t)e.y * 16 + q, v);
    }
}

// ---------------------------------------------------------------------------
// K4: finalize. Untouched -> zeros to out; touched -> transpose scratch tile.
__global__ void finalize_kernel(float* __restrict__ out) {
    __shared__ float tile[64][65];
    int blk  = blockIdx.x;                 // NTILES
    int b    = blk / TILES_PER_B;
    int tIdx = blk - b * TILES_PER_B;
    int pos0 = tIdx * 64;
    int t    = threadIdx.x;                // 256

    float* dst = out + (size_t)b * Cn * VOX_PER_B + pos0;

    if (g_touched[blk] == 0) {
        float4 z = make_float4(0.f, 0.f, 0.f, 0.f);
        #pragma unroll
        for (int k = 0; k < 4; k++) {
            int i = t + 256 * k;           // 0..1023 float4 slots
            int c = i >> 4;
            int p = (i & 15) * 4;
            __stcs(reinterpret_cast<float4*>(dst + (size_t)c * VOX_PER_B + p), z);
        }
        return;
    }

    const float4* src4 = reinterpret_cast<const float4*>(g_scratch) + (size_t)blk * 1024;
    #pragma unroll
    for (int k = 0; k < 4; k++) {
        int i = t + 256 * k;
        float4 v = src4[i];
        int pos = i >> 4;
        int c4  = (i & 15) * 4;
        tile[pos][c4 + 0] = v.x;
        tile[pos][c4 + 1] = v.y;
        tile[pos][c4 + 2] = v.z;
        tile[pos][c4 + 3] = v.w;
    }
    __syncthreads();

    #pragma unroll
    for (int k = 0; k < 4; k++) {
        int i = t + 256 * k;
        int c = i >> 4;
        int p = (i & 15) * 4;
        float4 v = make_float4(tile[p + 0][c], tile[p + 1][c],
                               tile[p + 2][c], tile[p + 3][c]);
        __stcs(reinterpret_cast<float4*>(dst + (size_t)c * VOX_PER_B + p), v);
    }
}

// ---------------------------------------------------------------------------
extern "C" void kernel_launch(void* const* d_in, const int* in_sizes, int n_in,
                              void* d_out, int out_size) {
    const float* x_feats    = (const float*)d_in[0];
    const float* rots       = (const float*)d_in[1];
    const float* trans      = (const float*)d_in[2];
    const float* intrins    = (const float*)d_in[3];
    const float* post_rots  = (const float*)d_in[4];
    const float* post_trans = (const float*)d_in[5];
    float* out = (float*)d_out;

    init_kernel<<<(NTILES + 255) / 256, 256>>>();
    geom_kernel<<<NPRIME / 256, 256>>>(rots, trans, intrins,
                                       post_rots, post_trans);
    zero_touched_kernel<<<NTILES, 256>>>();
    scatter_kernel<<<SCAT_BLOCKS, 256>>>(reinterpret_cast<const float4*>(x_feats));
    finalize_kernel<<<NTILES, 256>>>(out);
}